// round 16
// baseline (speedup 1.0000x reference)
#include <cuda_runtime.h>
#include <cuda_fp16.h>
#include <mma.h>
#include <math.h>
#include <stdint.h>

using namespace nvcuda;

#define NN 10000
#define NPAD 10112            // 79 * 128
#define NE 160000
#define HASH_BITS 19
#define HASH_SIZE (1<<HASH_BITS)
#define HASH_MASK (HASH_SIZE-1)

// ---------------- device scratch ----------------
__device__ float g_ek [(size_t)NE*128];
__device__ float g_upd[(size_t)NE*128];
__device__ float g_x  [NN*128];
__device__ float g_nq [NPAD*128];
__device__ float g_nv [NPAD*128];
__device__ float g_und [NPAD*128];
__device__ float g_eatt[NPAD*128];
__device__ unsigned g_agg[NN*128];
__device__ float g_outf[NN*128];
__device__ float g_incf[NN*128];
__device__ int   g_rev [NE];
__device__ int   g_hkey[HASH_SIZE];
__device__ int   g_hval[HASH_SIZE];
__device__ int   g_cout[NN];
__device__ int   g_cin [NN];
// fp16 operands
__device__ __half g_xh[NPAD*128];
__device__ __half g_efh[(size_t)NE*128];
__device__ __half g_hidh[(size_t)NE*384];
__device__ __half g_ncat_h[NPAD*256];
__device__ __half g_acat_h[NPAD*256];
__device__ __half g_nhid_h[NPAD*256];
// prepped fp16 weight blobs ([k32][n128] tiles of 4096):
// eW1:0(196608) eW2:196608(49152) kW:245760(16384) qW:262144(16384)
// vW:278528(16384) nW1:294912(65536) nW2:360448(32768) aW:393216(32768)
__device__ __half g_wh[425984];

#define NEGINF_ENC 0x007FFFFFu

// ---------------- cp.async helpers ----------------
__device__ __forceinline__ void cp16(unsigned dst, const void* src) {
    asm volatile("cp.async.cg.shared.global [%0], [%1], 16;" :: "r"(dst), "l"(src));
}
__device__ __forceinline__ void cp_commit() { asm volatile("cp.async.commit_group;" ::: "memory"); }
__device__ __forceinline__ void cp_wait0()  { asm volatile("cp.async.wait_group 0;" ::: "memory"); }

// ---------------- precompute kernels ----------------
__global__ void k_pre_init(int n) {
    int i = blockIdx.x * 256 + threadIdx.x;
    if (i < HASH_SIZE) { g_hkey[i] = -1; g_hval[i] = 0x7FFFFFFF; }
    if (i < n) { g_cout[i] = 0; g_cin[i] = 0; }
}
__global__ void k_hash_insert(const int* __restrict__ row, const int* __restrict__ col, int E, int N) {
    int e = blockIdx.x * 256 + threadIdx.x;
    if (e >= E) return;
    int r = row[e], c = col[e];
    atomicAdd(&g_cout[r], 1);
    atomicAdd(&g_cin[c], 1);
    int key = r * N + c;
    unsigned slot = ((unsigned)key * 2654435761u) & HASH_MASK;
    while (true) {
        int old = atomicCAS(&g_hkey[slot], -1, key);
        if (old == -1 || old == key) { atomicMin(&g_hval[slot], e); break; }
        slot = (slot + 1) & HASH_MASK;
    }
}
__global__ void k_rev_lookup(const int* __restrict__ row, const int* __restrict__ col, int E, int N) {
    int e = blockIdx.x * 256 + threadIdx.x;
    if (e >= E) return;
    int rkey = col[e] * N + row[e];
    unsigned slot = ((unsigned)rkey * 2654435761u) & HASH_MASK;
    int rv = -1;
    while (true) {
        int k = g_hkey[slot];
        if (k == rkey) { rv = g_hval[slot]; break; }
        if (k == -1) break;
        slot = (slot + 1) & HASH_MASK;
    }
    g_rev[e] = rv;
}
__global__ void k_layer_init(int n128) {
    int i = blockIdx.x * 256 + threadIdx.x;
    if (i >= n128) return;
    g_outf[i] = 0.f; g_incf[i] = 0.f; g_agg[i] = NEGINF_ENC;
}

// ---------------- fused weight prep: all 8 weight matrices -> fp16 blobs ----------------
__global__ void k_wprep_all(const float* __restrict__ eW1, const float* __restrict__ eW2,
                            const float* __restrict__ kW,  const float* __restrict__ qW,
                            const float* __restrict__ vW,  const float* __restrict__ nW1,
                            const float* __restrict__ nW2, const float* __restrict__ aW) {
    int idx = blockIdx.x * 256 + threadIdx.x;
    if (idx >= 425984) return;
    const float* W; int Kf, Nf; int li = idx;
    if (idx < 196608)      { W = eW1; Kf = 512; Nf = 384; }
    else if (idx < 245760) { W = eW2; Kf = 384; Nf = 128; li -= 196608; }
    else if (idx < 262144) { W = kW;  Kf = 128; Nf = 128; li -= 245760; }
    else if (idx < 278528) { W = qW;  Kf = 128; Nf = 128; li -= 262144; }
    else if (idx < 294912) { W = vW;  Kf = 128; Nf = 128; li -= 278528; }
    else if (idx < 360448) { W = nW1; Kf = 256; Nf = 256; li -= 294912; }
    else if (idx < 393216) { W = nW2; Kf = 256; Nf = 128; li -= 360448; }
    else                   { W = aW;  Kf = 256; Nf = 128; li -= 393216; }
    int t = li >> 12, wi = li & 4095;
    int k = wi >> 7, n = wi & 127;
    int kct = Kf >> 5;
    int ntile = t / kct, kch = t % kct;
    float w = W[(size_t)(kch * 32 + k) * Nf + ntile * 128 + n];
    g_wh[idx] = __float2half_rn(w);
}

// ---------------- fp32 -> fp16 convert (vectorized) ----------------
__global__ void k_cvt(const float* __restrict__ src, __half* __restrict__ dh, int n4) {
    int i = blockIdx.x * 256 + threadIdx.x;
    if (i >= n4) return;
    float4 v = ((const float4*)src)[i];
    __half2 hh[2] = {__floats2half2_rn(v.x, v.y), __floats2half2_rn(v.z, v.w)};
    *(uint2*)(dh + 4 * (size_t)i) = *(uint2*)hh;
}

// fused: scatter(upd+eB2) into outf/incf AND ef = relu(upd+eB2) -> fp16
__global__ void k_scatter_efsplit(const float* __restrict__ ue, const float* __restrict__ eb2,
                                  const int* __restrict__ row, const int* __restrict__ col, int E) {
    int i = blockIdx.x * 256 + threadIdx.x;
    if (i >= E * 32) return;
    int e = i >> 5, c4 = (i & 31) * 4;
    float4 v = ((const float4*)ue)[i];
    v.x += eb2[c4]; v.y += eb2[c4 + 1]; v.z += eb2[c4 + 2]; v.w += eb2[c4 + 3];
    float* po = g_outf + (size_t)row[e] * 128 + c4;
    float* pi = g_incf + (size_t)col[e] * 128 + c4;
    atomicAdd(po, v.x); atomicAdd(po + 1, v.y); atomicAdd(po + 2, v.z); atomicAdd(po + 3, v.w);
    atomicAdd(pi, v.x); atomicAdd(pi + 1, v.y); atomicAdd(pi + 2, v.z); atomicAdd(pi + 3, v.w);
    __half2 hh[2] = {__floats2half2_rn(fmaxf(v.x, 0.f), fmaxf(v.y, 0.f)),
                     __floats2half2_rn(fmaxf(v.z, 0.f), fmaxf(v.w, 0.f))};
    *(uint2*)(g_efh + 4 * (size_t)i) = *(uint2*)hh;
}

// fused: scatter(upd+eB2) AND write biased value back (final-layer out_ef)
__global__ void k_scatter_bias(float* __restrict__ ue, const float* __restrict__ eb2,
                               const int* __restrict__ row, const int* __restrict__ col, int E) {
    int i = blockIdx.x * 256 + threadIdx.x;
    if (i >= E * 32) return;
    int e = i >> 5, c4 = (i & 31) * 4;
    float4 v = ((float4*)ue)[i];
    v.x += eb2[c4]; v.y += eb2[c4 + 1]; v.z += eb2[c4 + 2]; v.w += eb2[c4 + 3];
    ((float4*)ue)[i] = v;
    float* po = g_outf + (size_t)row[e] * 128 + c4;
    float* pi = g_incf + (size_t)col[e] * 128 + c4;
    atomicAdd(po, v.x); atomicAdd(po + 1, v.y); atomicAdd(po + 2, v.z); atomicAdd(po + 3, v.w);
    atomicAdd(pi, v.x); atomicAdd(pi + 1, v.y); atomicAdd(pi + 2, v.z); atomicAdd(pi + 3, v.w);
}

// ---------------- shared GEMM config (fp16 single-pass, 64-wide K-chunks) ----------------
// 128x128 CTA tile, 256 threads (8 warps: 4M x 2N), 2 CTAs/SM.
// Double-buffered 64-wide K-chunks (two 32-k weight blobs, contiguous), all cp.async.
// smem fp16: A(buf)=buf*9216 (128 rows x 72); B base 18432: buf*8704 (64 k x 136).
// Mainloop = 71680B; fp32 epilogue staging needs 67584B <= that.
#define MG_SMEM  71680

// ---------------- persistent GEMM (dense A, raw fp32 out) ----------------
// KCT = number of 64-wide chunks (Kf / 64)
template<int KCT>
__global__ void __launch_bounds__(256, 2)
k_pgemm(const __half* __restrict__ Ah, int wbase, float* __restrict__ Cf, int Nf, int nmb) {
    extern __shared__ char smc[];
    uint32_t smb = (uint32_t)__cvta_generic_to_shared(smc);
    const int Kf = KCT * 64;
    int tid = threadIdx.x;
    int w = tid >> 5, wm = w & 3, wn = w >> 2;
    int ntile = blockIdx.y;
    int ar = tid >> 1, hf = tid & 1;   // A: row, 32-elt half of 64
    int bk = tid >> 2, bq = tid & 3;   // B: k-row (0..63), 32-elt quarter

    wmma::fragment<wmma::accumulator, 16, 16, 16, float> acc[2][4];
#pragma unroll
    for (int i = 0; i < 2; i++)
#pragma unroll
        for (int j = 0; j < 4; j++) wmma::fill_fragment(acc[i][j], 0.f);

    int sblk = blockIdx.x, skc = 0;
    auto stage = [&](int buf) {
        // B: two consecutive 4096-elt blobs (8192 contiguous halves)
        size_t blob = (size_t)wbase + (size_t)(ntile * KCT * 2 + skc * 2) * 4096 + bk * 128 + bq * 32;
        uint32_t dB = smb + (18432 + buf * 8704 + bk * 136 + bq * 32) * 2;
#pragma unroll
        for (int c = 0; c < 4; c++) cp16(dB + c * 16, g_wh + blob + c * 8);
        // A: 32 halves per thread
        size_t e = (size_t)sblk * 128 + ar;
        const __half* sA = Ah + e * Kf + skc * 64 + hf * 32;
        uint32_t dA = smb + (buf * 9216 + ar * 72 + hf * 32) * 2;
#pragma unroll
        for (int c = 0; c < 4; c++) cp16(dA + c * 16, sA + c * 8);
    };

    stage(0); cp_commit();
    if (++skc == KCT) { skc = 0; sblk += gridDim.x; }
    int buf = 0;
    const __half* sm = (const __half*)smc;

    for (int cblk = blockIdx.x; cblk < nmb; cblk += gridDim.x) {
        for (int kc = 0; kc < KCT; kc++) {
            cp_wait0();
            __syncthreads();
            if (sblk < nmb) {
                stage(buf ^ 1); cp_commit();
                if (++skc == KCT) { skc = 0; sblk += gridDim.x; }
            }
            const __half* A_H = sm + buf * 9216;
            const __half* B_H = sm + 18432 + buf * 8704;
#pragma unroll
            for (int ks = 0; ks < 4; ks++) {
                wmma::fragment<wmma::matrix_a, 16, 16, 16, __half, wmma::row_major> af[2];
                wmma::fragment<wmma::matrix_b, 16, 16, 16, __half, wmma::row_major> bf[4];
#pragma unroll
                for (int i = 0; i < 2; i++)
                    wmma::load_matrix_sync(af[i], A_H + (wm * 32 + i * 16) * 72 + ks * 16, 72);
#pragma unroll
                for (int j = 0; j < 4; j++)
                    wmma::load_matrix_sync(bf[j], B_H + (ks * 16) * 136 + wn * 64 + j * 16, 136);
#pragma unroll
                for (int i = 0; i < 2; i++)
#pragma unroll
                    for (int j = 0; j < 4; j++)
                        wmma::mma_sync(acc[i][j], af[i], bf[j], acc[i][j]);
            }
            buf ^= 1;
        }
        size_t mbase = (size_t)cblk * 128;
#pragma unroll
        for (int i = 0; i < 2; i++)
#pragma unroll
            for (int j = 0; j < 4; j++) {
                wmma::store_matrix_sync(
                    Cf + (mbase + wm * 32 + i * 16) * Nf + (size_t)ntile * 128 + wn * 64 + j * 16,
                    acc[i][j], Nf, wmma::mem_row_major);
                wmma::fill_fragment(acc[i][j], 0.f);
            }
    }
}

// ---------------- per-block GEMM with epilogue ----------------
// EPI 2: bias+sigmoid -> Cf fp32.  EPI 3: bias+relu -> Ch fp16.
// GATHER: A row e = concat[x[row] | ef[e] | ef[rev] | x[col]] (Kf=512, seg = kc>>1).
template<int EPI, int GATHER>
__global__ void __launch_bounds__(256, 2)
k_mgemm(const __half* __restrict__ Ah, int Kf, int wbase, const float* __restrict__ bias,
        float* __restrict__ Cf, __half* __restrict__ Ch,
        int Nf, const int* __restrict__ row, const int* __restrict__ col) {
    extern __shared__ char smc[];
    __half* sm = (__half*)smc;
    uint32_t smb = (uint32_t)__cvta_generic_to_shared(smc);
    int tid = threadIdx.x;
    int w = tid >> 5, wm = w & 3, wn = w >> 2;
    size_t mbase = (size_t)blockIdx.x * 128;
    int ntile = blockIdx.y;
    int kct = Kf >> 6;                 // 64-wide chunks

    int ar = tid >> 1, hf2 = tid & 1;
    size_t e = mbase + ar;
    int ri = 0, ci = 0, rvv = -1;
    if (GATHER) { ri = row[e]; ci = col[e]; rvv = g_rev[e]; }
    int bk = tid >> 2, bq = tid & 3;

    wmma::fragment<wmma::accumulator, 16, 16, 16, float> acc[2][4];
#pragma unroll
    for (int i = 0; i < 2; i++)
#pragma unroll
        for (int j = 0; j < 4; j++) wmma::fill_fragment(acc[i][j], 0.f);

    auto stage = [&](int kc, int buf) {
        size_t blob = (size_t)wbase + (size_t)(ntile * kct * 2 + kc * 2) * 4096 + bk * 128 + bq * 32;
        uint32_t dB = smb + (18432 + buf * 8704 + bk * 136 + bq * 32) * 2;
#pragma unroll
        for (int c = 0; c < 4; c++) cp16(dB + c * 16, g_wh + blob + c * 8);
        const __half* sA = nullptr;
        if (!GATHER) {
            sA = Ah + e * Kf + kc * 64 + hf2 * 32;
        } else {
            int seg = kc >> 1, o = (kc & 1) * 64 + hf2 * 32;
            if (seg == 0)      sA = g_xh + (size_t)ri * 128 + o;
            else if (seg == 1) sA = g_efh + e * 128 + o;
            else if (seg == 2) { if (rvv >= 0) sA = g_efh + (size_t)rvv * 128 + o; }
            else               sA = g_xh + (size_t)ci * 128 + o;
        }
        uint32_t dA = smb + (buf * 9216 + ar * 72 + hf2 * 32) * 2;
        if (sA) {
#pragma unroll
            for (int c = 0; c < 4; c++) cp16(dA + c * 16, sA + c * 8);
        } else {
            uint4 z = make_uint4(0, 0, 0, 0);
            __half* p = sm + buf * 9216 + ar * 72 + hf2 * 32;
#pragma unroll
            for (int c = 0; c < 4; c++) *(uint4*)(p + c * 8) = z;
        }
    };

    stage(0, 0); cp_commit();
    int buf = 0;
    for (int kc = 0; kc < kct; kc++) {
        cp_wait0();
        __syncthreads();
        if (kc + 1 < kct) { stage(kc + 1, buf ^ 1); cp_commit(); }
        const __half* A_H = sm + buf * 9216;
        const __half* B_H = sm + 18432 + buf * 8704;
#pragma unroll
        for (int ks = 0; ks < 4; ks++) {
            wmma::fragment<wmma::matrix_a, 16, 16, 16, __half, wmma::row_major> af[2];
            wmma::fragment<wmma::matrix_b, 16, 16, 16, __half, wmma::row_major> bf[4];
#pragma unroll
            for (int i = 0; i < 2; i++)
                wmma::load_matrix_sync(af[i], A_H + (wm * 32 + i * 16) * 72 + ks * 16, 72);
#pragma unroll
            for (int j = 0; j < 4; j++)
                wmma::load_matrix_sync(bf[j], B_H + (ks * 16) * 136 + wn * 64 + j * 16, 136);
#pragma unroll
            for (int i = 0; i < 2; i++)
#pragma unroll
                for (int j = 0; j < 4; j++)
                    wmma::mma_sync(acc[i][j], af[i], bf[j], acc[i][j]);
        }
        buf ^= 1;
    }

    __syncthreads();
    float* stg = (float*)smc;
#pragma unroll
    for (int i = 0; i < 2; i++)
#pragma unroll
        for (int j = 0; j < 4; j++)
            wmma::store_matrix_sync(stg + (wm * 32 + i * 16) * 132 + wn * 64 + j * 16,
                                    acc[i][j], 132, wmma::mem_row_major);
    __syncthreads();
    int hf = tid & 1;
    int lr = tid >> 1;
    size_t er = mbase + lr;
    const float* sr = stg + lr * 132 + hf * 64;
    const float* bb = bias + ntile * 128 + hf * 64;
    if (EPI == 3) {
        __half* oh = Ch + er * Nf + ntile * 128 + hf * 64;
#pragma unroll
        for (int g = 0; g < 8; g++) {
            __half2 hh[4];
#pragma unroll
            for (int p = 0; p < 4; p++) {
                float a = fmaxf(sr[g * 8 + 2 * p]     + bb[g * 8 + 2 * p],     0.f);
                float b = fmaxf(sr[g * 8 + 2 * p + 1] + bb[g * 8 + 2 * p + 1], 0.f);
                hh[p] = __floats2half2_rn(a, b);
            }
            *(uint4*)(oh + g * 8) = *(uint4*)hh;
        }
    } else {  // EPI == 2: bias + sigmoid -> fp32
        float* of = Cf + er * Nf + ntile * 128 + hf * 64;
#pragma unroll
        for (int g = 0; g < 16; g++) {
            float a = sr[g * 4],     b = sr[g * 4 + 1];
            float c = sr[g * 4 + 2], d = sr[g * 4 + 3];
            a = 1.f / (1.f + expf(-(a + bb[g * 4])));
            b = 1.f / (1.f + expf(-(b + bb[g * 4 + 1])));
            c = 1.f / (1.f + expf(-(c + bb[g * 4 + 2])));
            d = 1.f / (1.f + expf(-(d + bb[g * 4 + 3])));
            *(float4*)(of + g * 4) = make_float4(a, b, c, d);
        }
    }
}

// ---------------- attention (kB/qB/vB biases folded in) ----------------
__launch_bounds__(256)
__global__ void k_attn(const float* __restrict__ desc,
                       const int* __restrict__ row, const int* __restrict__ col,
                       const float* __restrict__ W1, const float* __restrict__ B1,
                       const float* __restrict__ W2, const float* __restrict__ B2,
                       const float* __restrict__ dW1, const float* __restrict__ dB1,
                       const float* __restrict__ dW2, const float* __restrict__ dB2,
                       const float* __restrict__ kB, const float* __restrict__ qB,
                       const float* __restrict__ vB,
                       float* __restrict__ probout, int E) {
    __shared__ float sW1[1024], sW2[512], sB1[32], sB2[16];
    __shared__ float sdW1[128], sdB1[32], sdW2[32], sdB2;
    __shared__ float sKB[128], sQB[128], sVB[128];
    int tid = threadIdx.x;
    for (int i = tid; i < 1024; i += 256) sW1[i] = W1[i];
    for (int i = tid; i < 512;  i += 256) sW2[i] = W2[i];
    if (tid < 32) { sB1[tid] = B1[tid]; sdB1[tid] = dB1[tid]; sdW2[tid] = dW2[tid]; }
    if (tid < 16) sB2[tid] = B2[tid];
    if (tid >= 32 && tid < 160) sdW1[tid - 32] = dW1[tid - 32];
    if (tid < 128) { sKB[tid] = kB[tid]; sQB[tid] = qB[tid]; sVB[tid] = vB[tid]; }
    if (tid == 0) sdB2 = dB2[0];
    __syncthreads();

    int gid = blockIdx.x * 256 + tid;
    if (gid >= E * 8) return;
    int e = gid >> 3, h = gid & 7;
    int r = row[e], c = col[e];

    float hv[32];
#pragma unroll
    for (int i = 0; i < 16; i++) hv[i]      = g_nq[(size_t)r * 128 + i * 8 + h] + sQB[i * 8 + h];
#pragma unroll
    for (int i = 0; i < 16; i++) hv[16 + i] = g_ek[(size_t)e * 128 + i * 8 + h] + sKB[i * 8 + h];

    float h1[32];
#pragma unroll
    for (int o = 0; o < 32; o++) {
        float s = sB1[o];
#pragma unroll
        for (int cc = 0; cc < 32; cc++) s += sW1[o * 32 + cc] * hv[cc];
        h1[o] = fmaxf(s, 0.f);
    }
    float att[16];
#pragma unroll
    for (int o = 0; o < 16; o++) {
        float s = sB2[o];
#pragma unroll
        for (int cc = 0; cc < 32; cc++) s += sW2[o * 32 + cc] * h1[cc];
        att[o] = s;
    }
    float dx = desc[r * 8 + 0] - desc[c * 8 + 0];
    float dy = desc[r * 8 + 1] - desc[c * 8 + 1];
    float dz = desc[r * 8 + 2] - desc[c * 8 + 2];
    float dist = sqrtf(dx * dx + dy * dy + dz * dz);
    float f4[4] = {dx, dy, dz, dist};
    float s2 = sdB2;
#pragma unroll
    for (int j = 0; j < 32; j++) {
        float z = sdB1[j];
#pragma unroll
        for (int i = 0; i < 4; i++) z += f4[i] * sdW1[i * 32 + j];
        s2 += fmaxf(z, 0.f) * sdW2[j];
    }
    float dm = 1.f / (1.f + expf(-s2));

    float m = -1e30f;
#pragma unroll
    for (int o = 0; o < 16; o++) { att[o] = att[o] * dm * 0.25f; m = fmaxf(m, att[o]); }
    float sum = 0.f;
#pragma unroll
    for (int o = 0; o < 16; o++) { att[o] = expf(att[o] - m); sum += att[o]; }
    float inv = 1.f / sum;
#pragma unroll
    for (int o = 0; o < 16; o++) {
        float p = att[o] * inv;
        probout[(size_t)e * 128 + o * 8 + h] = p;
        float wv = p * (g_nv[(size_t)c * 128 + o * 8 + h] + sVB[o * 8 + h]);
        unsigned u = __float_as_uint(wv);
        u = (u & 0x80000000u) ? ~u : (u | 0x80000000u);
        atomicMax(&g_agg[r * 128 + o * 8 + h], u);
    }
}

// ---------------- small kernels ----------------
__global__ void k_ncat(const float* __restrict__ x, int n) {
    int idx = blockIdx.x * 256 + threadIdx.x;
    if (idx >= n * 256) return;
    int nd = idx >> 8, cc = idx & 255;
    float v;
    if (cc < 128) v = x[nd * 128 + cc];
    else {
        unsigned u = g_agg[nd * 128 + cc - 128];
        float f = (u & 0x80000000u) ? __uint_as_float(u ^ 0x80000000u) : __uint_as_float(~u);
        v = (u == NEGINF_ENC) ? 0.f : f;
    }
    g_ncat_h[idx] = __float2half_rn(v);
}
__global__ void k_acat(int n) {
    int idx = blockIdx.x * 256 + threadIdx.x;
    if (idx >= n * 256) return;
    int nd = idx >> 8, cc = idx & 255;
    float v;
    if (cc < 128) v = g_outf[nd * 128 + cc] / fmaxf((float)g_cout[nd], 1.f);
    else          v = g_incf[nd * 128 + cc - 128] / fmaxf((float)g_cin[nd], 1.f);
    g_acat_h[idx] = __float2half_rn(v);
}
template<int SPL>
__global__ void k_final(float* __restrict__ dst, const float* __restrict__ nb2, int n) {
    int idx = blockIdx.x * 256 + threadIdx.x;
    if (idx >= n * 128) return;
    float v = fmaxf(g_und[idx] + nb2[idx & 127], 0.f) * g_eatt[idx];
    dst[idx] = v;
    if (SPL) g_xh[idx] = __float2half_rn(v);
}

// ---------------- host side ----------------
static void* symaddr(const void* s) { void* p = nullptr; cudaGetSymbolAddress(&p, s); return p; }

#define PGRID 304   // 2 CTAs per SM (edge GEMMs)
#define NMB_N 79    // node M-blocks (10112 / 128)

extern "C" void kernel_launch(void* const* d_in, const int* in_sizes, int n_in,
                              void* d_out, int out_size) {
    const float* x0   = (const float*)d_in[0];
    const float* ef0  = (const float*)d_in[1];
    const int*   eidx = (const int*)d_in[2];
    const float* desc = (const float*)d_in[3];
    const float* qW   = (const float*)d_in[4];
    const float* qB   = (const float*)d_in[5];
    const float* kW   = (const float*)d_in[6];
    const float* kB   = (const float*)d_in[7];
    const float* vW   = (const float*)d_in[8];
    const float* vB   = (const float*)d_in[9];
    const float* dW1  = (const float*)d_in[10];
    const float* dB1  = (const float*)d_in[11];
    const float* dW2  = (const float*)d_in[12];
    const float* dB2  = (const float*)d_in[13];
    const float* eW1  = (const float*)d_in[14];
    const float* eB1  = (const float*)d_in[15];
    const float* eW2  = (const float*)d_in[16];
    const float* eB2  = (const float*)d_in[17];
    const float* aW1  = (const float*)d_in[18];
    const float* aB1  = (const float*)d_in[19];
    const float* aW2  = (const float*)d_in[20];
    const float* aB2  = (const float*)d_in[21];
    const float* nW1  = (const float*)d_in[22];
    const float* nB1  = (const float*)d_in[23];
    const float* nW2  = (const float*)d_in[24];
    const float* nB2  = (const float*)d_in[25];
    const float* aW   = (const float*)d_in[26];
    const float* aB   = (const float*)d_in[27];

    int N = in_sizes[0] / 128;   // 10000
    int E = in_sizes[1] / 128;   // 160000
    const int* row = eidx;
    const int* col = eidx + E;

    float* out      = (float*)d_out;
    float* out_x    = out;
    float* out_ef   = out + (size_t)N * 128;
    float* out_prob = out_ef + (size_t)E * 128;

    float* p_ek   = (float*)symaddr(g_ek);
    float* p_upd  = (float*)symaddr(g_upd);
    float* p_x    = (float*)symaddr(g_x);
    float* p_nq   = (float*)symaddr(g_nq);
    float* p_nv   = (float*)symaddr(g_nv);
    float* p_und  = (float*)symaddr(g_und);
    float* p_eatt = (float*)symaddr(g_eatt);
    __half* p_xh    = (__half*)symaddr(g_xh);
    __half* p_efh   = (__half*)symaddr(g_efh);
    __half* p_hidh  = (__half*)symaddr(g_hidh);
    __half* p_ncath = (__half*)symaddr(g_ncat_h);
    __half* p_acath = (__half*)symaddr(g_acat_h);
    __half* p_nhidh = (__half*)symaddr(g_nhid_h);

    cudaFuncSetAttribute(k_mgemm<3,1>, cudaFuncAttributeMaxDynamicSharedMemorySize, MG_SMEM);
    cudaFuncSetAttribute(k_mgemm<3,0>, cudaFuncAttributeMaxDynamicSharedMemorySize, MG_SMEM);
    cudaFuncSetAttribute(k_mgemm<2,0>, cudaFuncAttributeMaxDynamicSharedMemorySize, MG_SMEM);
    cudaFuncSetAttribute(k_pgemm<2>,  cudaFuncAttributeMaxDynamicSharedMemorySize, MG_SMEM);
    cudaFuncSetAttribute(k_pgemm<4>,  cudaFuncAttributeMaxDynamicSharedMemorySize, MG_SMEM);
    cudaFuncSetAttribute(k_pgemm<6>,  cudaFuncAttributeMaxDynamicSharedMemorySize, MG_SMEM);

    const int WB_E1 = 0, WB_E2 = 196608, WB_K = 245760, WB_Q = 262144,
              WB_V = 278528, WB_N1 = 294912, WB_N2 = 360448, WB_A = 393216;
    int nmb = E / 128;

    // ---- layer-0 prep ----
    k_wprep_all<<<1664, 256>>>(eW1, eW2, kW, qW, vW, nW1, nW2, aW);            // #1
    k_cvt<<<(E * 32 + 255) / 256, 256>>>(ef0, p_efh, E * 32);                  // #2
    k_cvt<<<(N * 32 + 255) / 256, 256>>>(x0,  p_xh,  N * 32);                  // #3
    k_pgemm<2><<<dim3(PGRID, 1), 256, MG_SMEM>>>(p_efh, WB_K, p_ek, 128, nmb); // #4
    k_pre_init<<<(HASH_SIZE + 255) / 256, 256>>>(N);                           // #5
    k_hash_insert<<<(E + 255) / 256, 256>>>(row, col, E, N);                   // #6
    k_rev_lookup<<<(E + 255) / 256, 256>>>(row, col, E, N);                    // #7

    const int L = 2;
    for (int l = 0; l < L; l++) {
        const float* xc  = (l == 0) ? x0 : p_x;
        float* upd_t = (l == L - 1) ? out_ef : p_upd;

        const float* qW_l  = qW  + (size_t)l * 128 * 128;
        const float* qB_l  = qB  + (size_t)l * 128;
        const float* kW_l  = kW  + (size_t)l * 128 * 128;
        const float* kB_l  = kB  + (size_t)l * 128;
        const float* vW_l  = vW  + (size_t)l * 128 * 128;
        const float* vB_l  = vB  + (size_t)l * 128;
        const float* dW1_l = dW1 + (size_t)l * 4 * 32;
        const float* dB1_l = dB1 + (size_t)l * 32;
        const float* dW2_l = dW2 + (size_t)l * 32;
        const float* dB2_l = dB2 + (size_t)l * 1;
        const float* eW1_l = eW1 + (size_t)l * 512 * 384;
        const float* eB1_l = eB1 + (size_t)l * 384;
        const float* eW2_l = eW2 + (size_t)l * 384 * 128;
        const float* eB2_l = eB2 + (size_t)l * 128;
        const float* aW1_l = aW1 + (size_t)l * 32 * 32;
        const float* aB1_l = aB1 + (size_t)l * 32;
        const float* aW2_l = aW2 + (size_t)l * 16 * 32;
        const float* aB2_l = aB2 + (size_t)l * 16;
        const float* nW1_l = nW1 + (size_t)l * 256 * 256;
        const float* nB1_l = nB1 + (size_t)l * 256;
        const float* nW2_l = nW2 + (size_t)l * 256 * 128;
        const float* nB2_l = nB2 + (size_t)l * 128;
        const float* aW_l  = aW  + (size_t)l * 256 * 128;
        const float* aB_l  = aB  + (size_t)l * 128;

        if (l > 0) {
            k_wprep_all<<<1664, 256>>>(eW1_l, eW2_l, kW_l, qW_l, vW_l, nW1_l, nW2_l, aW_l);
            k_pgemm<2><<<dim3(PGRID, 1), 256, MG_SMEM>>>(p_efh, WB_K, p_ek, 128, nmb);
        }

        k_layer_init<<<(N * 128 + 255) / 256, 256>>>(N * 128);

        // node-level q, v (tensor, raw; qB/vB folded into k_attn)
        k_pgemm<2><<<dim3(NMB_N, 1), 256, MG_SMEM>>>(p_xh, WB_Q, p_nq, 128, NMB_N);
        k_pgemm<2><<<dim3(NMB_N, 1), 256, MG_SMEM>>>(p_xh, WB_V, p_nv, 128, NMB_N);

        // edge MLP: GEMM1 (gather fused, bias+relu->fp16) ; GEMM2 (persistent, raw out)
        k_mgemm<3,1><<<dim3(E / 128, 3), 256, MG_SMEM>>>(
            nullptr, 512, WB_E1, eB1_l, nullptr, p_hidh, 384, row, col);
        k_pgemm<6><<<dim3(PGRID, 1), 256, MG_SMEM>>>(p_hidh, WB_E2, upd_t, 128, nmb);

        // attention -> prob out + segment_max(wv)
        k_attn<<<(E * 8 + 255) / 256, 256>>>(desc, row, col,
                                             aW1_l, aB1_l, aW2_l, aB2_l,
                                             dW1_l, dB1_l, dW2_l, dB2_l,
                                             kB_l, qB_l, vB_l,
                                             out_prob + (size_t)l * E * 128, E);

        // fused: segment sums (eB2 folded) + ef relu/cvt or final bias
        if (l < L - 1)
            k_scatter_efsplit<<<(E * 32 + 255) / 256, 256>>>(upd_t, eB2_l, row, col, E);
        else
            k_scatter_bias<<<(E * 32 + 255) / 256, 256>>>(upd_t, eB2_l, row, col, E);

        // node MLP (tensor): ncat -> nhid (bias+relu fp16) -> und (raw; nB2 in k_final)
        k_ncat<<<(N * 256 + 255) / 256, 256>>>(xc, N);
        k_mgemm<3,0><<<dim3(NMB_N, 2), 256, MG_SMEM>>>(
            p_ncath, 256, WB_N1, nB1_l, nullptr, p_nhidh, 256, nullptr, nullptr);
        k_pgemm<4><<<dim3(NMB_N, 1), 256, MG_SMEM>>>(p_nhidh, WB_N2, p_und, 128, NMB_N);

        // edge-attention gate (tensor, bias+sigmoid)
        k_acat<<<(N * 256 + 255) / 256, 256>>>(N);
        k_mgemm<2,0><<<dim3(NMB_N, 1), 256, MG_SMEM>>>(
            p_acath, 256, WB_A, aB_l, p_eatt, nullptr, 128, nullptr, nullptr);

        if (l < L - 1)
            k_final<1><<<(N * 128 + 255) / 256, 256>>>(p_x, nB2_l, N);
        else
            k_final<0><<<(N * 128 + 255) / 256, 256>>>(out_x, nB2_l, N);
    }
}

// round 17
// speedup vs baseline: 1.0905x; 1.0905x over previous
#include <cuda_runtime.h>
#include <cuda_fp16.h>
#include <mma.h>
#include <math.h>
#include <stdint.h>

using namespace nvcuda;

#define NN 10000
#define NPAD 10112            // 79 * 128
#define NE 160000
#define HASH_BITS 19
#define HASH_SIZE (1<<HASH_BITS)
#define HASH_MASK (HASH_SIZE-1)

// ---------------- device scratch ----------------
__device__ float g_ek [(size_t)NE*128];
__device__ float g_upd[(size_t)NE*128];
__device__ float g_x  [NN*128];
__device__ float g_nq [NPAD*128];
__device__ float g_nv [NPAD*128];
__device__ float g_und [NPAD*128];
__device__ float g_eatt[NPAD*128];
__device__ unsigned g_agg[NN*128];
__device__ float g_outf[NN*128];
__device__ float g_incf[NN*128];
__device__ int   g_rev [NE];
__device__ int   g_hkey[HASH_SIZE];
__device__ int   g_hval[HASH_SIZE];
__device__ int   g_cout[NN];
__device__ int   g_cin [NN];
// fp16 operands
__device__ __half g_xh[NPAD*128];
__device__ __half g_efh[(size_t)NE*128];
__device__ __half g_hidh[(size_t)NE*384];
__device__ __half g_ncat_h[NPAD*256];
__device__ __half g_acat_h[NPAD*256];
__device__ __half g_nhid_h[NPAD*256];
// prepped fp16 weight blobs ([k32][n128] tiles of 4096):
// eW1:0(196608) eW2:196608(49152) kW:245760(16384) qW:262144(16384)
// vW:278528(16384) nW1:294912(65536) nW2:360448(32768) aW:393216(32768)
__device__ __half g_wh[425984];

#define NEGINF_ENC 0x007FFFFFu

// ---------------- cp.async helpers ----------------
__device__ __forceinline__ void cp16(unsigned dst, const void* src) {
    asm volatile("cp.async.cg.shared.global [%0], [%1], 16;" :: "r"(dst), "l"(src));
}
__device__ __forceinline__ void cp_commit() { asm volatile("cp.async.commit_group;" ::: "memory"); }
__device__ __forceinline__ void cp_wait0()  { asm volatile("cp.async.wait_group 0;" ::: "memory"); }

// ---------------- precompute kernels ----------------
__global__ void k_pre_init(int n) {
    int i = blockIdx.x * 256 + threadIdx.x;
    if (i < HASH_SIZE) { g_hkey[i] = -1; g_hval[i] = 0x7FFFFFFF; }
    if (i < n) { g_cout[i] = 0; g_cin[i] = 0; }
}
__global__ void k_hash_insert(const int* __restrict__ row, const int* __restrict__ col, int E, int N) {
    int e = blockIdx.x * 256 + threadIdx.x;
    if (e >= E) return;
    int r = row[e], c = col[e];
    atomicAdd(&g_cout[r], 1);
    atomicAdd(&g_cin[c], 1);
    int key = r * N + c;
    unsigned slot = ((unsigned)key * 2654435761u) & HASH_MASK;
    while (true) {
        int old = atomicCAS(&g_hkey[slot], -1, key);
        if (old == -1 || old == key) { atomicMin(&g_hval[slot], e); break; }
        slot = (slot + 1) & HASH_MASK;
    }
}
__global__ void k_rev_lookup(const int* __restrict__ row, const int* __restrict__ col, int E, int N) {
    int e = blockIdx.x * 256 + threadIdx.x;
    if (e >= E) return;
    int rkey = col[e] * N + row[e];
    unsigned slot = ((unsigned)rkey * 2654435761u) & HASH_MASK;
    int rv = -1;
    while (true) {
        int k = g_hkey[slot];
        if (k == rkey) { rv = g_hval[slot]; break; }
        if (k == -1) break;
        slot = (slot + 1) & HASH_MASK;
    }
    g_rev[e] = rv;
}
__global__ void k_layer_init(int n128) {
    int i = blockIdx.x * 256 + threadIdx.x;
    if (i >= n128) return;
    g_outf[i] = 0.f; g_incf[i] = 0.f; g_agg[i] = NEGINF_ENC;
}

// ---------------- fused weight prep: all 8 weight matrices -> fp16 blobs ----------------
__global__ void k_wprep_all(const float* __restrict__ eW1, const float* __restrict__ eW2,
                            const float* __restrict__ kW,  const float* __restrict__ qW,
                            const float* __restrict__ vW,  const float* __restrict__ nW1,
                            const float* __restrict__ nW2, const float* __restrict__ aW) {
    int idx = blockIdx.x * 256 + threadIdx.x;
    if (idx >= 425984) return;
    const float* W; int Kf, Nf; int li = idx;
    if (idx < 196608)      { W = eW1; Kf = 512; Nf = 384; }
    else if (idx < 245760) { W = eW2; Kf = 384; Nf = 128; li -= 196608; }
    else if (idx < 262144) { W = kW;  Kf = 128; Nf = 128; li -= 245760; }
    else if (idx < 278528) { W = qW;  Kf = 128; Nf = 128; li -= 262144; }
    else if (idx < 294912) { W = vW;  Kf = 128; Nf = 128; li -= 278528; }
    else if (idx < 360448) { W = nW1; Kf = 256; Nf = 256; li -= 294912; }
    else if (idx < 393216) { W = nW2; Kf = 256; Nf = 128; li -= 360448; }
    else                   { W = aW;  Kf = 256; Nf = 128; li -= 393216; }
    int t = li >> 12, wi = li & 4095;
    int k = wi >> 7, n = wi & 127;
    int kct = Kf >> 5;
    int ntile = t / kct, kch = t % kct;
    float w = W[(size_t)(kch * 32 + k) * Nf + ntile * 128 + n];
    g_wh[idx] = __float2half_rn(w);
}

// ---------------- fp32 -> fp16 convert (vectorized) ----------------
__global__ void k_cvt(const float* __restrict__ src, __half* __restrict__ dh, int n4) {
    int i = blockIdx.x * 256 + threadIdx.x;
    if (i >= n4) return;
    float4 v = ((const float4*)src)[i];
    __half2 hh[2] = {__floats2half2_rn(v.x, v.y), __floats2half2_rn(v.z, v.w)};
    *(uint2*)(dh + 4 * (size_t)i) = *(uint2*)hh;
}

// fused: scatter(upd+eB2) into outf/incf AND ef = relu(upd+eB2) -> fp16
__global__ void k_scatter_efsplit(const float* __restrict__ ue, const float* __restrict__ eb2,
                                  const int* __restrict__ row, const int* __restrict__ col, int E) {
    int i = blockIdx.x * 256 + threadIdx.x;
    if (i >= E * 32) return;
    int e = i >> 5, c4 = (i & 31) * 4;
    float4 v = ((const float4*)ue)[i];
    v.x += eb2[c4]; v.y += eb2[c4 + 1]; v.z += eb2[c4 + 2]; v.w += eb2[c4 + 3];
    float* po = g_outf + (size_t)row[e] * 128 + c4;
    float* pi = g_incf + (size_t)col[e] * 128 + c4;
    atomicAdd(po, v.x); atomicAdd(po + 1, v.y); atomicAdd(po + 2, v.z); atomicAdd(po + 3, v.w);
    atomicAdd(pi, v.x); atomicAdd(pi + 1, v.y); atomicAdd(pi + 2, v.z); atomicAdd(pi + 3, v.w);
    __half2 hh[2] = {__floats2half2_rn(fmaxf(v.x, 0.f), fmaxf(v.y, 0.f)),
                     __floats2half2_rn(fmaxf(v.z, 0.f), fmaxf(v.w, 0.f))};
    *(uint2*)(g_efh + 4 * (size_t)i) = *(uint2*)hh;
}

// fused: scatter(upd+eB2) AND write biased value back (final-layer out_ef)
__global__ void k_scatter_bias(float* __restrict__ ue, const float* __restrict__ eb2,
                               const int* __restrict__ row, const int* __restrict__ col, int E) {
    int i = blockIdx.x * 256 + threadIdx.x;
    if (i >= E * 32) return;
    int e = i >> 5, c4 = (i & 31) * 4;
    float4 v = ((float4*)ue)[i];
    v.x += eb2[c4]; v.y += eb2[c4 + 1]; v.z += eb2[c4 + 2]; v.w += eb2[c4 + 3];
    ((float4*)ue)[i] = v;
    float* po = g_outf + (size_t)row[e] * 128 + c4;
    float* pi = g_incf + (size_t)col[e] * 128 + c4;
    atomicAdd(po, v.x); atomicAdd(po + 1, v.y); atomicAdd(po + 2, v.z); atomicAdd(po + 3, v.w);
    atomicAdd(pi, v.x); atomicAdd(pi + 1, v.y); atomicAdd(pi + 2, v.z); atomicAdd(pi + 3, v.w);
}

// ---------------- shared GEMM config (fp16 single-pass, 32-wide K-chunks) ----------------
// 128x128 CTA tile, 256 threads (8 warps: 4M x 2N), 2 CTAs/SM.
// Double-buffered 32-wide K-chunks, all cp.async.
// smem fp16: A(buf)=buf*5120 (128 rows x 40); B base 10240: buf*4352 (32 k x 136).
#define MG_SMEM  37888
#define MG1_SMEM 67584

// ---------------- persistent GEMM (dense A, raw fp32 out) ----------------
template<int KCT>
__global__ void __launch_bounds__(256, 2)
k_pgemm(const __half* __restrict__ Ah, int wbase, float* __restrict__ Cf, int Nf, int nmb) {
    extern __shared__ char smc[];
    uint32_t smb = (uint32_t)__cvta_generic_to_shared(smc);
    const int Kf = KCT * 32;
    int tid = threadIdx.x;
    int w = tid >> 5, wm = w & 3, wn = w >> 2;
    int ntile = blockIdx.y;
    int ar = tid >> 1, ah = tid & 1;
    int bk = tid >> 3, bq = tid & 7;

    wmma::fragment<wmma::accumulator, 16, 16, 16, float> acc[2][4];
#pragma unroll
    for (int i = 0; i < 2; i++)
#pragma unroll
        for (int j = 0; j < 4; j++) wmma::fill_fragment(acc[i][j], 0.f);

    int sblk = blockIdx.x, skc = 0;
    auto stage = [&](int buf) {
        size_t blob = (size_t)wbase + (size_t)(ntile * KCT + skc) * 4096 + bk * 128 + bq * 16;
        uint32_t dB = smb + (10240 + buf * 4352 + bk * 136 + bq * 16) * 2;
        cp16(dB,      g_wh + blob);
        cp16(dB + 16, g_wh + blob + 8);
        size_t e = (size_t)sblk * 128 + ar;
        const __half* sA = Ah + e * Kf + skc * 32 + ah * 16;
        uint32_t dA = smb + (buf * 5120 + ar * 40 + ah * 16) * 2;
        cp16(dA,      sA);
        cp16(dA + 16, sA + 8);
    };

    stage(0); cp_commit();
    if (++skc == KCT) { skc = 0; sblk += gridDim.x; }
    int buf = 0;
    const __half* sm = (const __half*)smc;

    for (int cblk = blockIdx.x; cblk < nmb; cblk += gridDim.x) {
        for (int kc = 0; kc < KCT; kc++) {
            cp_wait0();
            __syncthreads();
            if (sblk < nmb) {
                stage(buf ^ 1); cp_commit();
                if (++skc == KCT) { skc = 0; sblk += gridDim.x; }
            }
            const __half* A_H = sm + buf * 5120;
            const __half* B_H = sm + 10240 + buf * 4352;
#pragma unroll
            for (int ks = 0; ks < 2; ks++) {
                wmma::fragment<wmma::matrix_a, 16, 16, 16, __half, wmma::row_major> af[2];
                wmma::fragment<wmma::matrix_b, 16, 16, 16, __half, wmma::row_major> bf[4];
#pragma unroll
                for (int i = 0; i < 2; i++)
                    wmma::load_matrix_sync(af[i], A_H + (wm * 32 + i * 16) * 40 + ks * 16, 40);
#pragma unroll
                for (int j = 0; j < 4; j++)
                    wmma::load_matrix_sync(bf[j], B_H + (ks * 16) * 136 + wn * 64 + j * 16, 136);
#pragma unroll
                for (int i = 0; i < 2; i++)
#pragma unroll
                    for (int j = 0; j < 4; j++)
                        wmma::mma_sync(acc[i][j], af[i], bf[j], acc[i][j]);
            }
            buf ^= 1;
        }
        size_t mbase = (size_t)cblk * 128;
#pragma unroll
        for (int i = 0; i < 2; i++)
#pragma unroll
            for (int j = 0; j < 4; j++) {
                wmma::store_matrix_sync(
                    Cf + (mbase + wm * 32 + i * 16) * Nf + (size_t)ntile * 128 + wn * 64 + j * 16,
                    acc[i][j], Nf, wmma::mem_row_major);
                wmma::fill_fragment(acc[i][j], 0.f);
            }
    }
}

// ---------------- per-block GEMM with epilogue ----------------
// EPI 2: bias+sigmoid -> Cf fp32.  EPI 3: bias+relu -> Ch fp16.
// GATHER: A row e = concat[x[row] | ef[e] | ef[rev] | x[col]] (Kf=512).
template<int EPI, int GATHER>
__global__ void __launch_bounds__(256, 2)
k_mgemm(const __half* __restrict__ Ah, int Kf, int wbase, const float* __restrict__ bias,
        float* __restrict__ Cf, __half* __restrict__ Ch,
        int Nf, const int* __restrict__ row, const int* __restrict__ col) {
    extern __shared__ char smc[];
    __half* sm = (__half*)smc;
    uint32_t smb = (uint32_t)__cvta_generic_to_shared(smc);
    int tid = threadIdx.x;
    int w = tid >> 5, wm = w & 3, wn = w >> 2;
    size_t mbase = (size_t)blockIdx.x * 128;
    int ntile = blockIdx.y;
    int kct = Kf >> 5;

    int ar = tid >> 1, ah = tid & 1;
    size_t e = mbase + ar;
    int ri = 0, ci = 0, rvv = -1;
    if (GATHER) { ri = row[e]; ci = col[e]; rvv = g_rev[e]; }
    int bk = tid >> 3, bq = tid & 7;

    wmma::fragment<wmma::accumulator, 16, 16, 16, float> acc[2][4];
#pragma unroll
    for (int i = 0; i < 2; i++)
#pragma unroll
        for (int j = 0; j < 4; j++) wmma::fill_fragment(acc[i][j], 0.f);

    auto stage = [&](int kc, int buf) {
        size_t blob = (size_t)wbase + (size_t)(ntile * kct + kc) * 4096 + bk * 128 + bq * 16;
        uint32_t dB = smb + (10240 + buf * 4352 + bk * 136 + bq * 16) * 2;
        cp16(dB,      g_wh + blob);
        cp16(dB + 16, g_wh + blob + 8);
        const __half* sA = nullptr;
        if (!GATHER) {
            sA = Ah + e * Kf + kc * 32 + ah * 16;
        } else {
            int seg = kc >> 2, o = (kc & 3) * 32 + ah * 16;
            if (seg == 0)      sA = g_xh + (size_t)ri * 128 + o;
            else if (seg == 1) sA = g_efh + e * 128 + o;
            else if (seg == 2) { if (rvv >= 0) sA = g_efh + (size_t)rvv * 128 + o; }
            else               sA = g_xh + (size_t)ci * 128 + o;
        }
        uint32_t dA = smb + (buf * 5120 + ar * 40 + ah * 16) * 2;
        if (sA) {
            cp16(dA,      sA);
            cp16(dA + 16, sA + 8);
        } else {
            uint4 z = make_uint4(0, 0, 0, 0);
            __half* p = sm + buf * 5120 + ar * 40 + ah * 16;
            *(uint4*)p = z; *(uint4*)(p + 8) = z;
        }
    };

    stage(0, 0); cp_commit();
    int buf = 0;
    for (int kc = 0; kc < kct; kc++) {
        cp_wait0();
        __syncthreads();
        if (kc + 1 < kct) { stage(kc + 1, buf ^ 1); cp_commit(); }
        const __half* A_H = sm + buf * 5120;
        const __half* B_H = sm + 10240 + buf * 4352;
#pragma unroll
        for (int ks = 0; ks < 2; ks++) {
            wmma::fragment<wmma::matrix_a, 16, 16, 16, __half, wmma::row_major> af[2];
            wmma::fragment<wmma::matrix_b, 16, 16, 16, __half, wmma::row_major> bf[4];
#pragma unroll
            for (int i = 0; i < 2; i++)
                wmma::load_matrix_sync(af[i], A_H + (wm * 32 + i * 16) * 40 + ks * 16, 40);
#pragma unroll
            for (int j = 0; j < 4; j++)
                wmma::load_matrix_sync(bf[j], B_H + (ks * 16) * 136 + wn * 64 + j * 16, 136);
#pragma unroll
            for (int i = 0; i < 2; i++)
#pragma unroll
                for (int j = 0; j < 4; j++)
                    wmma::mma_sync(acc[i][j], af[i], bf[j], acc[i][j]);
        }
        buf ^= 1;
    }

    __syncthreads();
    float* stg = (float*)smc;
#pragma unroll
    for (int i = 0; i < 2; i++)
#pragma unroll
        for (int j = 0; j < 4; j++)
            wmma::store_matrix_sync(stg + (wm * 32 + i * 16) * 132 + wn * 64 + j * 16,
                                    acc[i][j], 132, wmma::mem_row_major);
    __syncthreads();
    int hf = tid & 1;
    int lr = tid >> 1;
    size_t er = mbase + lr;
    const float* sr = stg + lr * 132 + hf * 64;
    const float* bb = bias + ntile * 128 + hf * 64;
    if (EPI == 3) {
        __half* oh = Ch + er * Nf + ntile * 128 + hf * 64;
#pragma unroll
        for (int g = 0; g < 8; g++) {
            __half2 hh[4];
#pragma unroll
            for (int p = 0; p < 4; p++) {
                float a = fmaxf(sr[g * 8 + 2 * p]     + bb[g * 8 + 2 * p],     0.f);
                float b = fmaxf(sr[g * 8 + 2 * p + 1] + bb[g * 8 + 2 * p + 1], 0.f);
                hh[p] = __floats2half2_rn(a, b);
            }
            *(uint4*)(oh + g * 8) = *(uint4*)hh;
        }
    } else {  // EPI == 2: bias + sigmoid -> fp32
        float* of = Cf + er * Nf + ntile * 128 + hf * 64;
#pragma unroll
        for (int g = 0; g < 16; g++) {
            float a = sr[g * 4],     b = sr[g * 4 + 1];
            float c = sr[g * 4 + 2], d = sr[g * 4 + 3];
            a = 1.f / (1.f + expf(-(a + bb[g * 4])));
            b = 1.f / (1.f + expf(-(b + bb[g * 4 + 1])));
            c = 1.f / (1.f + expf(-(c + bb[g * 4 + 2])));
            d = 1.f / (1.f + expf(-(d + bb[g * 4 + 3])));
            *(float4*)(of + g * 4) = make_float4(a, b, c, d);
        }
    }
}

// ---------------- attention (kB/qB/vB folded; distance-gate split across 8 lanes) ----------------
__launch_bounds__(256)
__global__ void k_attn(const float* __restrict__ desc,
                       const int* __restrict__ row, const int* __restrict__ col,
                       const float* __restrict__ W1, const float* __restrict__ B1,
                       const float* __restrict__ W2, const float* __restrict__ B2,
                       const float* __restrict__ dW1, const float* __restrict__ dB1,
                       const float* __restrict__ dW2, const float* __restrict__ dB2,
                       const float* __restrict__ kB, const float* __restrict__ qB,
                       const float* __restrict__ vB,
                       float* __restrict__ probout, int E) {
    __shared__ float sW1[1024], sW2[512], sB1[32], sB2[16];
    __shared__ float sdW1[128], sdB1[32], sdW2[32], sdB2;
    __shared__ float sKB[128], sQB[128], sVB[128];
    int tid = threadIdx.x;
    for (int i = tid; i < 1024; i += 256) sW1[i] = W1[i];
    for (int i = tid; i < 512;  i += 256) sW2[i] = W2[i];
    if (tid < 32) { sB1[tid] = B1[tid]; sdB1[tid] = dB1[tid]; sdW2[tid] = dW2[tid]; }
    if (tid < 16) sB2[tid] = B2[tid];
    if (tid >= 32 && tid < 160) sdW1[tid - 32] = dW1[tid - 32];
    if (tid < 128) { sKB[tid] = kB[tid]; sQB[tid] = qB[tid]; sVB[tid] = vB[tid]; }
    if (tid == 0) sdB2 = dB2[0];
    __syncthreads();

    int gid = blockIdx.x * 256 + tid;
    if (gid >= E * 8) return;       // E*8 divisible by 256 -> full warps
    int e = gid >> 3, h = gid & 7;
    int r = row[e], c = col[e];

    float hv[32];
#pragma unroll
    for (int i = 0; i < 16; i++) hv[i]      = g_nq[(size_t)r * 128 + i * 8 + h] + sQB[i * 8 + h];
#pragma unroll
    for (int i = 0; i < 16; i++) hv[16 + i] = g_ek[(size_t)e * 128 + i * 8 + h] + sKB[i * 8 + h];

    float h1[32];
#pragma unroll
    for (int o = 0; o < 32; o++) {
        float s = sB1[o];
#pragma unroll
        for (int cc = 0; cc < 32; cc++) s += sW1[o * 32 + cc] * hv[cc];
        h1[o] = fmaxf(s, 0.f);
    }
    float att[16];
#pragma unroll
    for (int o = 0; o < 16; o++) {
        float s = sB2[o];
#pragma unroll
        for (int cc = 0; cc < 32; cc++) s += sW2[o * 32 + cc] * h1[cc];
        att[o] = s;
    }
    // distance gate: 32 hidden units split 4-per-lane across the 8 lanes of this edge
    float dx = desc[r * 8 + 0] - desc[c * 8 + 0];
    float dy = desc[r * 8 + 1] - desc[c * 8 + 1];
    float dz = desc[r * 8 + 2] - desc[c * 8 + 2];
    float dist = sqrtf(dx * dx + dy * dy + dz * dz);
    float f4[4] = {dx, dy, dz, dist};
    float s2 = 0.f;
#pragma unroll
    for (int jj = 0; jj < 4; jj++) {
        int j = h * 4 + jj;
        float z = sdB1[j];
#pragma unroll
        for (int i = 0; i < 4; i++) z += f4[i] * sdW1[i * 32 + j];
        s2 += fmaxf(z, 0.f) * sdW2[j];
    }
    s2 += __shfl_xor_sync(0xFFFFFFFFu, s2, 1);
    s2 += __shfl_xor_sync(0xFFFFFFFFu, s2, 2);
    s2 += __shfl_xor_sync(0xFFFFFFFFu, s2, 4);
    float dm = 1.f / (1.f + expf(-(s2 + sdB2)));

    float m = -1e30f;
#pragma unroll
    for (int o = 0; o < 16; o++) { att[o] = att[o] * dm * 0.25f; m = fmaxf(m, att[o]); }
    float sum = 0.f;
#pragma unroll
    for (int o = 0; o < 16; o++) { att[o] = expf(att[o] - m); sum += att[o]; }
    float inv = 1.f / sum;
#pragma unroll
    for (int o = 0; o < 16; o++) {
        float p = att[o] * inv;
        probout[(size_t)e * 128 + o * 8 + h] = p;
        float wv = p * (g_nv[(size_t)c * 128 + o * 8 + h] + sVB[o * 8 + h]);
        unsigned u = __float_as_uint(wv);
        u = (u & 0x80000000u) ? ~u : (u | 0x80000000u);
        atomicMax(&g_agg[r * 128 + o * 8 + h], u);
    }
}

// ---------------- small kernels ----------------
__global__ void k_ncat(const float* __restrict__ x, int n) {
    int idx = blockIdx.x * 256 + threadIdx.x;
    if (idx >= n * 256) return;
    int nd = idx >> 8, cc = idx & 255;
    float v;
    if (cc < 128) v = x[nd * 128 + cc];
    else {
        unsigned u = g_agg[nd * 128 + cc - 128];
        float f = (u & 0x80000000u) ? __uint_as_float(u ^ 0x80000000u) : __uint_as_float(~u);
        v = (u == NEGINF_ENC) ? 0.f : f;
    }
    g_ncat_h[idx] = __float2half_rn(v);
}
__global__ void k_acat(int n) {
    int idx = blockIdx.x * 256 + threadIdx.x;
    if (idx >= n * 256) return;
    int nd = idx >> 8, cc = idx & 255;
    float v;
    if (cc < 128) v = g_outf[nd * 128 + cc] / fmaxf((float)g_cout[nd], 1.f);
    else          v = g_incf[nd * 128 + cc - 128] / fmaxf((float)g_cin[nd], 1.f);
    g_acat_h[idx] = __float2half_rn(v);
}
template<int SPL>
__global__ void k_final(float* __restrict__ dst, const float* __restrict__ nb2, int n) {
    int idx = blockIdx.x * 256 + threadIdx.x;
    if (idx >= n * 128) return;
    float v = fmaxf(g_und[idx] + nb2[idx & 127], 0.f) * g_eatt[idx];
    dst[idx] = v;
    if (SPL) g_xh[idx] = __float2half_rn(v);
}

// ---------------- host side ----------------
static void* symaddr(const void* s) { void* p = nullptr; cudaGetSymbolAddress(&p, s); return p; }

#define PGRID 304   // 2 CTAs per SM (edge GEMMs)
#define NMB_N 79    // node M-blocks (10112 / 128)

extern "C" void kernel_launch(void* const* d_in, const int* in_sizes, int n_in,
                              void* d_out, int out_size) {
    const float* x0   = (const float*)d_in[0];
    const float* ef0  = (const float*)d_in[1];
    const int*   eidx = (const int*)d_in[2];
    const float* desc = (const float*)d_in[3];
    const float* qW   = (const float*)d_in[4];
    const float* qB   = (const float*)d_in[5];
    const float* kW   = (const float*)d_in[6];
    const float* kB   = (const float*)d_in[7];
    const float* vW   = (const float*)d_in[8];
    const float* vB   = (const float*)d_in[9];
    const float* dW1  = (const float*)d_in[10];
    const float* dB1  = (const float*)d_in[11];
    const float* dW2  = (const float*)d_in[12];
    const float* dB2  = (const float*)d_in[13];
    const float* eW1  = (const float*)d_in[14];
    const float* eB1  = (const float*)d_in[15];
    const float* eW2  = (const float*)d_in[16];
    const float* eB2  = (const float*)d_in[17];
    const float* aW1  = (const float*)d_in[18];
    const float* aB1  = (const float*)d_in[19];
    const float* aW2  = (const float*)d_in[20];
    const float* aB2  = (const float*)d_in[21];
    const float* nW1  = (const float*)d_in[22];
    const float* nB1  = (const float*)d_in[23];
    const float* nW2  = (const float*)d_in[24];
    const float* nB2  = (const float*)d_in[25];
    const float* aW   = (const float*)d_in[26];
    const float* aB   = (const float*)d_in[27];

    int N = in_sizes[0] / 128;   // 10000
    int E = in_sizes[1] / 128;   // 160000
    const int* row = eidx;
    const int* col = eidx + E;

    float* out      = (float*)d_out;
    float* out_x    = out;
    float* out_ef   = out + (size_t)N * 128;
    float* out_prob = out_ef + (size_t)E * 128;

    float* p_ek   = (float*)symaddr(g_ek);
    float* p_upd  = (float*)symaddr(g_upd);
    float* p_x    = (float*)symaddr(g_x);
    float* p_nq   = (float*)symaddr(g_nq);
    float* p_nv   = (float*)symaddr(g_nv);
    float* p_und  = (float*)symaddr(g_und);
    float* p_eatt = (float*)symaddr(g_eatt);
    __half* p_xh    = (__half*)symaddr(g_xh);
    __half* p_efh   = (__half*)symaddr(g_efh);
    __half* p_hidh  = (__half*)symaddr(g_hidh);
    __half* p_ncath = (__half*)symaddr(g_ncat_h);
    __half* p_acath = (__half*)symaddr(g_acat_h);
    __half* p_nhidh = (__half*)symaddr(g_nhid_h);

    cudaFuncSetAttribute(k_mgemm<3,1>, cudaFuncAttributeMaxDynamicSharedMemorySize, MG1_SMEM);
    cudaFuncSetAttribute(k_mgemm<3,0>, cudaFuncAttributeMaxDynamicSharedMemorySize, MG1_SMEM);
    cudaFuncSetAttribute(k_mgemm<2,0>, cudaFuncAttributeMaxDynamicSharedMemorySize, MG1_SMEM);
    cudaFuncSetAttribute(k_pgemm<4>,  cudaFuncAttributeMaxDynamicSharedMemorySize, MG_SMEM);
    cudaFuncSetAttribute(k_pgemm<8>,  cudaFuncAttributeMaxDynamicSharedMemorySize, MG_SMEM);
    cudaFuncSetAttribute(k_pgemm<12>, cudaFuncAttributeMaxDynamicSharedMemorySize, MG_SMEM);

    const int WB_E1 = 0, WB_E2 = 196608, WB_K = 245760, WB_Q = 262144,
              WB_V = 278528, WB_N1 = 294912, WB_N2 = 360448, WB_A = 393216;
    int nmb = E / 128;

    // ---- layer-0 prep ----
    k_wprep_all<<<1664, 256>>>(eW1, eW2, kW, qW, vW, nW1, nW2, aW);            // #1
    k_cvt<<<(E * 32 + 255) / 256, 256>>>(ef0, p_efh, E * 32);                  // #2
    k_cvt<<<(N * 32 + 255) / 256, 256>>>(x0,  p_xh,  N * 32);                  // #3
    k_pgemm<4><<<dim3(PGRID, 1), 256, MG_SMEM>>>(p_efh, WB_K, p_ek, 128, nmb); // #4
    k_pre_init<<<(HASH_SIZE + 255) / 256, 256>>>(N);                           // #5
    k_hash_insert<<<(E + 255) / 256, 256>>>(row, col, E, N);                   // #6
    k_rev_lookup<<<(E + 255) / 256, 256>>>(row, col, E, N);                    // #7

    const int L = 2;
    for (int l = 0; l < L; l++) {
        const float* xc  = (l == 0) ? x0 : p_x;
        float* upd_t = (l == L - 1) ? out_ef : p_upd;

        const float* qW_l  = qW  + (size_t)l * 128 * 128;
        const float* qB_l  = qB  + (size_t)l * 128;
        const float* kW_l  = kW  + (size_t)l * 128 * 128;
        const float* kB_l  = kB  + (size_t)l * 128;
        const float* vW_l  = vW  + (size_t)l * 128 * 128;
        const float* vB_l  = vB  + (size_t)l * 128;
        const float* dW1_l = dW1 + (size_t)l * 4 * 32;
        const float* dB1_l = dB1 + (size_t)l * 32;
        const float* dW2_l = dW2 + (size_t)l * 32;
        const float* dB2_l = dB2 + (size_t)l * 1;
        const float* eW1_l = eW1 + (size_t)l * 512 * 384;
        const float* eB1_l = eB1 + (size_t)l * 384;
        const float* eW2_l = eW2 + (size_t)l * 384 * 128;
        const float* eB2_l = eB2 + (size_t)l * 128;
        const float* aW1_l = aW1 + (size_t)l * 32 * 32;
        const float* aB1_l = aB1 + (size_t)l * 32;
        const float* aW2_l = aW2 + (size_t)l * 16 * 32;
        const float* aB2_l = aB2 + (size_t)l * 16;
        const float* nW1_l = nW1 + (size_t)l * 256 * 256;
        const float* nB1_l = nB1 + (size_t)l * 256;
        const float* nW2_l = nW2 + (size_t)l * 256 * 128;
        const float* nB2_l = nB2 + (size_t)l * 128;
        const float* aW_l  = aW  + (size_t)l * 256 * 128;
        const float* aB_l  = aB  + (size_t)l * 128;

        if (l > 0) {
            k_wprep_all<<<1664, 256>>>(eW1_l, eW2_l, kW_l, qW_l, vW_l, nW1_l, nW2_l, aW_l);
            k_pgemm<4><<<dim3(PGRID, 1), 256, MG_SMEM>>>(p_efh, WB_K, p_ek, 128, nmb);
        }

        k_layer_init<<<(N * 128 + 255) / 256, 256>>>(N * 128);

        // node-level q, v (tensor, raw; qB/vB folded into k_attn)
        k_pgemm<4><<<dim3(NMB_N, 1), 256, MG_SMEM>>>(p_xh, WB_Q, p_nq, 128, NMB_N);
        k_pgemm<4><<<dim3(NMB_N, 1), 256, MG_SMEM>>>(p_xh, WB_V, p_nv, 128, NMB_N);

        // edge MLP: GEMM1 (gather fused, bias+relu->fp16) ; GEMM2 (persistent, raw out)
        k_mgemm<3,1><<<dim3(E / 128, 3), 256, MG1_SMEM>>>(
            nullptr, 512, WB_E1, eB1_l, nullptr, p_hidh, 384, row, col);
        k_pgemm<12><<<dim3(PGRID, 1), 256, MG_SMEM>>>(p_hidh, WB_E2, upd_t, 128, nmb);

        // attention -> prob out + segment_max(wv)
        k_attn<<<(E * 8 + 255) / 256, 256>>>(desc, row, col,
                                             aW1_l, aB1_l, aW2_l, aB2_l,
                                             dW1_l, dB1_l, dW2_l, dB2_l,
                                             kB_l, qB_l, vB_l,
                                             out_prob + (size_t)l * E * 128, E);

        // fused: segment sums (eB2 folded) + ef relu/cvt or final bias
        if (l < L - 1)
            k_scatter_efsplit<<<(E * 32 + 255) / 256, 256>>>(upd_t, eB2_l, row, col, E);
        else
            k_scatter_bias<<<(E * 32 + 255) / 256, 256>>>(upd_t, eB2_l, row, col, E);

        // node MLP (tensor): ncat -> nhid (bias+relu fp16) -> und (raw; nB2 in k_final)
        k_ncat<<<(N * 256 + 255) / 256, 256>>>(xc, N);
        k_mgemm<3,0><<<dim3(NMB_N, 2), 256, MG1_SMEM>>>(
            p_ncath, 256, WB_N1, nB1_l, nullptr, p_nhidh, 256, nullptr, nullptr);
        k_pgemm<8><<<dim3(NMB_N, 1), 256, MG_SMEM>>>(p_nhidh, WB_N2, p_und, 128, NMB_N);

        // edge-attention gate (tensor, bias+sigmoid)
        k_acat<<<(N * 256 + 255) / 256, 256>>>(N);
        k_mgemm<2,0><<<dim3(NMB_N, 1), 256, MG1_SMEM>>>(
            p_acath, 256, WB_A, aB_l, p_eatt, nullptr, 128, nullptr, nullptr);

        if (l < L - 1)
            k_final<1><<<(N * 128 + 255) / 256, 256>>>(p_x, nB2_l, N);
        else
            k_final<0><<<(N * 128 + 255) / 256, 256>>>(out_x, nB2_l, N);
    }
}